// round 2
// baseline (speedup 1.0000x reference)
#include <cuda_runtime.h>

// BatchHardLoss fused kernel, round 1 (fp32 SIMT GEMM + fused epilogue).
// W = clip(X@X^T * GAMMA, -16, 16); per-row pos_sum = sum_{same class, j!=i} exp(-W),
// neg_sum = sum_{diff class} exp(W); out = mean(log(pos_sum*neg_sum)).

#define BATCH 8192
#define DIMK  256
#define GAMMA 0.001f

static __device__ float g_pos[BATCH];
static __device__ float g_neg[BATCH];

constexpr int BM = 128;
constexpr int BN = 128;
constexpr int KB = 8;
constexpr int NSPLIT = 4;
constexpr int SPLIT_COLS = BATCH / NSPLIT;   // 2048
constexpr int NTILES = SPLIT_COLS / BN;      // 16
constexpr int KSTEPS = DIMK / KB;            // 32

__global__ void bhl_zero_kernel() {
    int i = blockIdx.x * blockDim.x + threadIdx.x;
    if (i < BATCH) { g_pos[i] = 0.0f; g_neg[i] = 0.0f; }
}

__global__ __launch_bounds__(256)
void bhl_main_kernel(const float* __restrict__ X, const int* __restrict__ T) {
    __shared__ float As[KB][BM];
    __shared__ float Bs[KB][BN];
    __shared__ int   tcolsh[BN];
    __shared__ float spos[BM];
    __shared__ float sneg[BM];

    const int tid = threadIdx.x;
    const int tx = tid & 15;          // 0..15 -> 8 cols each
    const int ty = tid >> 4;          // 0..15 -> 8 rows each
    const int rowBase  = blockIdx.x * BM;
    const int colBase0 = blockIdx.y * SPLIT_COLS;

    // global-load mapping: 2 threads per row, each loads a float4 (4 k-values)
    const int loadRow = tid >> 1;         // 0..127
    const int loadK   = (tid & 1) * 4;    // 0 or 4

    float acc[8][8];
#pragma unroll
    for (int i = 0; i < 8; i++)
#pragma unroll
        for (int j = 0; j < 8; j++) acc[i][j] = 0.0f;

    float posp[8], negp[8];
#pragma unroll
    for (int i = 0; i < 8; i++) { posp[i] = 0.0f; negp[i] = 0.0f; }

    int trow_r[8];
#pragma unroll
    for (int i = 0; i < 8; i++) trow_r[i] = T[rowBase + ty * 8 + i];

    const float* Arow = X + (size_t)(rowBase + loadRow) * DIMK + loadK;

    for (int t = 0; t < NTILES; ++t) {
        const int jBase = colBase0 + t * BN;
        __syncthreads();  // previous tile's epilogue done before tcolsh rewrite
        if (tid < BN) tcolsh[tid] = T[jBase + tid];

        const float* Brow = X + (size_t)(jBase + loadRow) * DIMK + loadK;

        float4 ra = *(const float4*)(Arow);
        float4 rb = *(const float4*)(Brow);

        for (int ks = 0; ks < KSTEPS; ++ks) {
            // store prefetched slab transposed into smem
            As[loadK + 0][loadRow] = ra.x;
            As[loadK + 1][loadRow] = ra.y;
            As[loadK + 2][loadRow] = ra.z;
            As[loadK + 3][loadRow] = ra.w;
            Bs[loadK + 0][loadRow] = rb.x;
            Bs[loadK + 1][loadRow] = rb.y;
            Bs[loadK + 2][loadRow] = rb.z;
            Bs[loadK + 3][loadRow] = rb.w;
            __syncthreads();

            if (ks + 1 < KSTEPS) {  // prefetch next slab while FMAs run
                ra = *(const float4*)(Arow + (ks + 1) * KB);
                rb = *(const float4*)(Brow + (ks + 1) * KB);
            }

#pragma unroll
            for (int kk = 0; kk < KB; kk++) {
                float4 a0 = *(const float4*)&As[kk][ty * 8];
                float4 a1 = *(const float4*)&As[kk][ty * 8 + 4];
                float4 b0 = *(const float4*)&Bs[kk][tx * 8];
                float4 b1 = *(const float4*)&Bs[kk][tx * 8 + 4];
                float av[8] = {a0.x, a0.y, a0.z, a0.w, a1.x, a1.y, a1.z, a1.w};
                float bv[8] = {b0.x, b0.y, b0.z, b0.w, b1.x, b1.y, b1.z, b1.w};
#pragma unroll
                for (int i = 0; i < 8; i++)
#pragma unroll
                    for (int j = 0; j < 8; j++)
                        acc[i][j] += av[i] * bv[j];
            }
            __syncthreads();
        }

        // fused epilogue for this 128x128 tile of W
        int tcol_r[8];
#pragma unroll
        for (int j = 0; j < 8; j++) tcol_r[j] = tcolsh[tx * 8 + j];

#pragma unroll
        for (int i = 0; i < 8; i++) {
            const int gR = rowBase + ty * 8 + i;
            const int ti = trow_r[i];
#pragma unroll
            for (int j = 0; j < 8; j++) {
                float w = acc[i][j] * GAMMA;
                w = fminf(fmaxf(w, -16.0f), 16.0f);
                const bool same = (ti == tcol_r[j]);
                const float e = __expf(same ? -w : w);
                const int gC = jBase + tx * 8 + j;
                if (same) {
                    if (gR != gC) posp[i] += e;
                } else {
                    negp[i] += e;
                }
                acc[i][j] = 0.0f;
            }
        }
    }

    // block-level per-row reduction, then one global atomic per row
    if (tid < BM) { spos[tid] = 0.0f; sneg[tid] = 0.0f; }
    __syncthreads();
#pragma unroll
    for (int i = 0; i < 8; i++) {
        atomicAdd(&spos[ty * 8 + i], posp[i]);
        atomicAdd(&sneg[ty * 8 + i], negp[i]);
    }
    __syncthreads();
    if (tid < BM) {
        atomicAdd(&g_pos[rowBase + tid], spos[tid]);
        atomicAdd(&g_neg[rowBase + tid], sneg[tid]);
    }
}

__global__ void bhl_finalize_kernel(float* __restrict__ out) {
    __shared__ float red[256];
    const int tid = threadIdx.x;
    float s = 0.0f;
    for (int r = tid; r < BATCH; r += 256)
        s += logf(g_pos[r] * g_neg[r]);
    red[tid] = s;
    __syncthreads();
    for (int off = 128; off > 0; off >>= 1) {
        if (tid < off) red[tid] += red[tid + off];
        __syncthreads();
    }
    if (tid == 0) out[0] = red[0] / (float)BATCH;
}

extern "C" void kernel_launch(void* const* d_in, const int* in_sizes, int n_in,
                              void* d_out, int out_size) {
    const float* X = (const float*)d_in[0];
    const int*   T = (const int*)d_in[1];
    float* out = (float*)d_out;

    bhl_zero_kernel<<<(BATCH + 255) / 256, 256>>>();
    dim3 grid(BATCH / BM, NSPLIT);
    bhl_main_kernel<<<grid, 256>>>(X, T);
    bhl_finalize_kernel<<<1, 256>>>(out);
}

// round 3
// speedup vs baseline: 6.5616x; 6.5616x over previous
#include <cuda_runtime.h>
#include <cuda_bf16.h>
#include <cstdint>

// BatchHardLoss round 2: bf16 mma.sync (m16n8k16) GEMM + fused epilogue in registers.

#define BATCH 8192
#define DIMK  256
#define GAMMA 0.001f

static __device__ float g_pos[BATCH];
static __device__ float g_neg[BATCH];
static __device__ __nv_bfloat16 g_Xb[BATCH * DIMK];

constexpr int BM = 128;
constexpr int BN = 128;
constexpr int KC = 64;                        // k-chunk (halves)
constexpr int NCHUNK = DIMK / KC;             // 4
constexpr int NSPLIT = 8;
constexpr int SPLIT_COLS = BATCH / NSPLIT;    // 1024
constexpr int NTILES = SPLIT_COLS / BN;       // 8

// dynamic smem: A resident 4 chunks x 16KB = 64KB, then B 2 bufs x 16KB = 32KB
constexpr int SMEM_A = 0;
constexpr int SMEM_B = 65536;
constexpr int SMEM_DYN = 98304;

#define SW128(o) ((o) ^ (((o) >> 3) & 0x70))

__global__ void bhl_zero_kernel() {
    int i = blockIdx.x * blockDim.x + threadIdx.x;
    if (i < BATCH) { g_pos[i] = 0.0f; g_neg[i] = 0.0f; }
}

__global__ void bhl_convert_kernel(const float* __restrict__ X) {
    int i = blockIdx.x * blockDim.x + threadIdx.x;   // float4 index
    float4 v = ((const float4*)X)[i];
    uint32_t lo = ((uint32_t)__bfloat16_as_ushort(__float2bfloat16_rn(v.y)) << 16)
                |  (uint32_t)__bfloat16_as_ushort(__float2bfloat16_rn(v.x));
    uint32_t hi = ((uint32_t)__bfloat16_as_ushort(__float2bfloat16_rn(v.w)) << 16)
                |  (uint32_t)__bfloat16_as_ushort(__float2bfloat16_rn(v.z));
    ((uint2*)g_Xb)[i] = make_uint2(lo, hi);
}

__device__ __forceinline__ void cp_async16(uint32_t dst, const void* src) {
    asm volatile("cp.async.cg.shared.global [%0], [%1], 16;\n" :: "r"(dst), "l"(src));
}
__device__ __forceinline__ void cp_commit() {
    asm volatile("cp.async.commit_group;\n" ::: "memory");
}

__global__ __launch_bounds__(256)
void bhl_main_kernel(const int* __restrict__ T) {
    extern __shared__ char dynsmem[];
    __shared__ int   tcolsh[BN];
    __shared__ float spos[BM];
    __shared__ float sneg[BM];

    const uint32_t sbase = (uint32_t)__cvta_generic_to_shared(dynsmem);
    const int tid  = threadIdx.x;
    const int lane = tid & 31;
    const int wid  = tid >> 5;
    const int wm   = wid >> 2;          // 0..1
    const int wn   = wid & 3;           // 0..3
    const int rowBase  = blockIdx.x * BM;
    const int colBase0 = blockIdx.y * SPLIT_COLS;

    if (tid < BM) { spos[tid] = 0.0f; sneg[tid] = 0.0f; }

    // ---- load A tile (128 x 256 bf16) into resident smem, SW128 per 16KB chunk ----
    {
        const char* Xb = (const char*)g_Xb;
#pragma unroll
        for (int i = 0; i < 16; i++) {
            int s = i * 256 + tid;           // 16B segment id, 0..4095
            int row = s >> 5;                // 0..127
            int seg = s & 31;                // 0..31
            int chunk = seg >> 3, w = seg & 7;
            uint32_t soff = SMEM_A + chunk * 16384 + SW128(row * 128 + w * 16);
            cp_async16(sbase + soff, Xb + (size_t)(rowBase + row) * 512 + seg * 16);
        }
        cp_commit();
    }

    // per-lane row classes: rows = wm*64 + mt*16 + (lane>>2) + h*8
    int trow[4][2];
#pragma unroll
    for (int mt = 0; mt < 4; mt++)
#pragma unroll
        for (int h = 0; h < 2; h++)
            trow[mt][h] = T[rowBase + wm * 64 + mt * 16 + (lane >> 2) + h * 8];

    float acc[4][4][4];
#pragma unroll
    for (int a = 0; a < 4; a++)
#pragma unroll
        for (int b = 0; b < 4; b++)
#pragma unroll
            for (int c = 0; c < 4; c++) acc[a][b][c] = 0.0f;

    float posp[8], negp[8];
#pragma unroll
    for (int i = 0; i < 8; i++) { posp[i] = 0.0f; negp[i] = 0.0f; }

    // B chunk loader
    auto loadB = [&](int nt, int nc, int buf) {
        const char* Xb = (const char*)g_Xb;
        const int jb = colBase0 + nt * BN;
#pragma unroll
        for (int i = 0; i < 4; i++) {
            int s = i * 256 + tid;           // 0..1023
            int n = s >> 3, w = s & 7;
            uint32_t soff = SMEM_B + buf * 16384 + SW128(n * 128 + w * 16);
            cp_async16(sbase + soff, Xb + (size_t)(jb + n) * 512 + nc * 128 + w * 16);
        }
        cp_commit();
    };

    loadB(0, 0, 0);

    for (int t = 0; t < NTILES; ++t) {
        const int jBase = colBase0 + t * BN;
        __syncthreads();                      // prev epilogue done before tcolsh rewrite
        if (tid < BN) tcolsh[tid] = T[jBase + tid];

        for (int c = 0; c < NCHUNK; ++c) {
            int nc = c + 1, nt = t;
            if (nc == NCHUNK) { nc = 0; nt = t + 1; }
            bool pref = (nt < NTILES);
            if (pref) loadB(nt, nc, nc & 1);
            if (pref) asm volatile("cp.async.wait_group 1;\n" ::: "memory");
            else      asm volatile("cp.async.wait_group 0;\n" ::: "memory");
            __syncthreads();

            const uint32_t aBase = sbase + SMEM_A + c * 16384;
            const uint32_t bBase = sbase + SMEM_B + (c & 1) * 16384;

#pragma unroll
            for (int ks = 0; ks < 4; ks++) {
                const int k0c = ks * 16;
                uint32_t af[4][4], bf[4][2];
#pragma unroll
                for (int mt = 0; mt < 4; mt++) {
                    int row = wm * 64 + mt * 16 + (lane & 15);
                    int kseg = (k0c >> 3) + (lane >> 4);
                    uint32_t addr = aBase + SW128(row * 128 + kseg * 16);
                    asm volatile("ldmatrix.sync.aligned.m8n8.x4.shared.b16 {%0,%1,%2,%3}, [%4];\n"
                                 : "=r"(af[mt][0]), "=r"(af[mt][1]), "=r"(af[mt][2]), "=r"(af[mt][3])
                                 : "r"(addr));
                }
#pragma unroll
                for (int nt2 = 0; nt2 < 4; nt2++) {
                    int n = wn * 32 + nt2 * 8 + (lane & 7);
                    int kseg = (k0c >> 3) + ((lane >> 3) & 1);
                    uint32_t addr = bBase + SW128(n * 128 + kseg * 16);
                    asm volatile("ldmatrix.sync.aligned.m8n8.x2.shared.b16 {%0,%1}, [%2];\n"
                                 : "=r"(bf[nt2][0]), "=r"(bf[nt2][1])
                                 : "r"(addr));
                }
#pragma unroll
                for (int mt = 0; mt < 4; mt++)
#pragma unroll
                    for (int nt2 = 0; nt2 < 4; nt2++) {
                        asm volatile(
                            "mma.sync.aligned.m16n8k16.row.col.f32.bf16.bf16.f32 "
                            "{%0,%1,%2,%3}, {%4,%5,%6,%7}, {%8,%9}, {%0,%1,%2,%3};\n"
                            : "+f"(acc[mt][nt2][0]), "+f"(acc[mt][nt2][1]),
                              "+f"(acc[mt][nt2][2]), "+f"(acc[mt][nt2][3])
                            : "r"(af[mt][0]), "r"(af[mt][1]), "r"(af[mt][2]), "r"(af[mt][3]),
                              "r"(bf[nt2][0]), "r"(bf[nt2][1]));
                    }
            }
            __syncthreads();                  // buffer reuse safety
        }

        // ---- fused epilogue on register fragments ----
#pragma unroll
        for (int mt = 0; mt < 4; mt++) {
            const int gRlo = rowBase + wm * 64 + mt * 16 + (lane >> 2);
            const int gRhi = gRlo + 8;
            const int trLo = trow[mt][0], trHi = trow[mt][1];
#pragma unroll
            for (int nt2 = 0; nt2 < 4; nt2++) {
                const int cb = wn * 32 + nt2 * 8 + 2 * (lane & 3);
                const int tc0 = tcolsh[cb], tc1 = tcolsh[cb + 1];
                const int gC0 = jBase + cb, gC1 = gC0 + 1;
#pragma unroll
                for (int e = 0; e < 4; e++) {
                    const int hi = e >> 1;            // 0: m-lo rows, 1: m-hi rows
                    const int cc = e & 1;
                    const int tr = hi ? trHi : trLo;
                    const int tc = cc ? tc1 : tc0;
                    const int gR = hi ? gRhi : gRlo;
                    const int gC = cc ? gC1 : gC0;
                    float w = acc[mt][nt2][e] * GAMMA;
                    w = fminf(fmaxf(w, -16.0f), 16.0f);
                    const bool same = (tr == tc);
                    const float ev = __expf(same ? -w : w);
                    if (same) {
                        if (gR != gC) posp[mt * 2 + hi] += ev;
                    } else {
                        negp[mt * 2 + hi] += ev;
                    }
                    acc[mt][nt2][e] = 0.0f;
                }
            }
        }
    }

    // ---- reduce: quad lanes (same rows) -> smem -> global atomics ----
#pragma unroll
    for (int i = 0; i < 8; i++) {
        float p = posp[i], n = negp[i];
        p += __shfl_xor_sync(0xffffffffu, p, 1);
        p += __shfl_xor_sync(0xffffffffu, p, 2);
        n += __shfl_xor_sync(0xffffffffu, n, 1);
        n += __shfl_xor_sync(0xffffffffu, n, 2);
        if ((lane & 3) == 0) {
            int r = wm * 64 + (i >> 1) * 16 + (lane >> 2) + (i & 1) * 8;
            atomicAdd(&spos[r], p);
            atomicAdd(&sneg[r], n);
        }
    }
    __syncthreads();
    if (tid < BM) {
        atomicAdd(&g_pos[rowBase + tid], spos[tid]);
        atomicAdd(&g_neg[rowBase + tid], sneg[tid]);
    }
}

__global__ void bhl_finalize_kernel(float* __restrict__ out) {
    __shared__ float red[256];
    const int tid = threadIdx.x;
    float s = 0.0f;
    for (int r = tid; r < BATCH; r += 256)
        s += logf(g_pos[r] * g_neg[r]);
    red[tid] = s;
    __syncthreads();
    for (int off = 128; off > 0; off >>= 1) {
        if (tid < off) red[tid] += red[tid + off];
        __syncthreads();
    }
    if (tid == 0) out[0] = red[0] / (float)BATCH;
}

extern "C" void kernel_launch(void* const* d_in, const int* in_sizes, int n_in,
                              void* d_out, int out_size) {
    const float* X = (const float*)d_in[0];
    const int*   T = (const int*)d_in[1];
    float* out = (float*)d_out;

    cudaFuncSetAttribute(bhl_main_kernel, cudaFuncAttributeMaxDynamicSharedMemorySize, SMEM_DYN);

    bhl_zero_kernel<<<(BATCH + 255) / 256, 256>>>();
    bhl_convert_kernel<<<(BATCH * DIMK / 4) / 256, 256>>>(X);
    dim3 grid(BATCH / BM, NSPLIT);
    bhl_main_kernel<<<grid, 256, SMEM_DYN>>>(T);
    bhl_finalize_kernel<<<1, 256>>>(out);
}